// round 6
// baseline (speedup 1.0000x reference)
#include <cuda_runtime.h>
#include <cuda_bf16.h>
#include <math.h>

#define D_FEAT    256
#define HW4       784             // float4 units per channel-image
#define NGRP      16
#define GS        16
#define NPOS      100352
#define NPOS4     25088
#define PAIRS     136
#define EPS_W     1e-6f

#define STATS_BY  27              // 16*27 = 432 blocks = 1 wave @ 3/SM
#define TILE      64              // float4 positions per smem tile
#define CHUNK     930             // ceil(NPOS4/27)
#define NTILES    15              // ceil(CHUNK/TILE)
#define APPLY_BY  18              // 16*18 = 288 blocks = 1 wave @ 2/SM

// Scratch (per-block partials, fully overwritten every launch)
__device__ float g_psum [NGRP][STATS_BY][GS];
__device__ float g_pprod[NGRP][STATS_BY][PAIRS];
__device__ float g_W[NGRP][GS * GS];
__device__ float g_b[NGRP][GS];

__device__ __forceinline__ float warp_sum(float v) {
    v += __shfl_down_sync(0xffffffffu, v, 16);
    v += __shfl_down_sync(0xffffffffu, v, 8);
    v += __shfl_down_sync(0xffffffffu, v, 4);
    v += __shfl_down_sync(0xffffffffu, v, 2);
    v += __shfl_down_sync(0xffffffffu, v, 1);
    return v;
}

// ---------------------------------------------------------------------------
// stats: cp.async-staged smem tiles, double buffered, 3 blocks/SM.
// (unchanged from R5 — measured 31.5us)
// ---------------------------------------------------------------------------
__global__ void __launch_bounds__(256, 3) stats_kernel(const float4* __restrict__ x4) {
    const int g   = blockIdx.x;
    const int by  = blockIdx.y;
    const int tid = threadIdx.x;

    const int P0 = by * CHUNK;
    const int P1 = (P0 + CHUNK < NPOS4) ? (P0 + CHUNK) : NPOS4;

    __shared__ float4 sbuf[2][GS * TILE];          // 2 x 16 KB
    __shared__ float rsum[GS];
    __shared__ float rpair[PAIRS];
    for (int i = tid; i < GS; i += 256) rsum[i] = 0.0f;
    for (int i = tid; i < PAIRS; i += 256) rpair[i] = 0.0f;

    const int li  = tid & 63;
    const int c0  = (tid >> 6) * 4;
    const int gch = g * GS;
    const unsigned sb = (unsigned)__cvta_generic_to_shared(&sbuf[0][0]);

    {
        const int pos = P0 + li;
        const unsigned sz = (pos < P1) ? 16u : 0u;
        const int pc = (pos < P1) ? pos : P0;
        const int m = pc / HW4;
        const int q = pc - m * HW4;
        const float4* src = x4 + (size_t)(m * D_FEAT + gch + c0) * HW4 + q;
        const unsigned dst = sb + (unsigned)((c0 * TILE + li) * 16);
#pragma unroll
        for (int j = 0; j < 4; j++)
            asm volatile("cp.async.cg.shared.global [%0], [%1], 16, %2;"
                         :: "r"(dst + j * TILE * 16), "l"(src + j * HW4), "r"(sz));
        asm volatile("cp.async.commit_group;" ::: "memory");
    }

    const int role = tid >> 6;
    const int ri   = tid & 63;
    const int lane = tid & 31;

    float acc[40];
#pragma unroll
    for (int i = 0; i < 40; i++) acc[i] = 0.0f;

    for (int t = 0; t < NTILES; t++) {
        asm volatile("cp.async.wait_group 0;" ::: "memory");
        __syncthreads();

        if (t + 1 < NTILES) {
            const int pos = P0 + (t + 1) * TILE + li;
            const unsigned sz = (pos < P1) ? 16u : 0u;
            const int pc = (pos < P1) ? pos : P0;
            const int m = pc / HW4;
            const int q = pc - m * HW4;
            const float4* src = x4 + (size_t)(m * D_FEAT + gch + c0) * HW4 + q;
            const unsigned dst = sb +
                (unsigned)((((t + 1) & 1) * GS * TILE + c0 * TILE + li) * 16);
#pragma unroll
            for (int j = 0; j < 4; j++)
                asm volatile("cp.async.cg.shared.global [%0], [%1], 16, %2;"
                             :: "r"(dst + j * TILE * 16), "l"(src + j * HW4), "r"(sz));
            asm volatile("cp.async.commit_group;" ::: "memory");
        }

        const float4* Bf = sbuf[t & 1];

        if (role == 0) {
            float4 v[8];
#pragma unroll
            for (int c = 0; c < 8; c++) v[c] = Bf[c * TILE + ri];
            int k = 0;
#pragma unroll
            for (int i = 0; i < 8; i++)
#pragma unroll
                for (int j = 0; j <= i; j++) {
                    acc[k] += v[i].x * v[j].x; acc[k] += v[i].y * v[j].y;
                    acc[k] += v[i].z * v[j].z; acc[k] += v[i].w * v[j].w;
                    k++;
                }
        } else if (role == 3) {
            float4 v[8];
#pragma unroll
            for (int c = 0; c < 8; c++) v[c] = Bf[(c + 8) * TILE + ri];
            int k = 0;
#pragma unroll
            for (int i = 0; i < 8; i++)
#pragma unroll
                for (int j = 0; j <= i; j++) {
                    acc[k] += v[i].x * v[j].x; acc[k] += v[i].y * v[j].y;
                    acc[k] += v[i].z * v[j].z; acc[k] += v[i].w * v[j].w;
                    k++;
                }
        } else {
            const int cb = (role == 1) ? 0 : 4;
            float4 vc[4];
#pragma unroll
            for (int c = 0; c < 4; c++) vc[c] = Bf[(cb + c) * TILE + ri];
#pragma unroll
            for (int c = 0; c < 4; c++)
                acc[32 + c] += (vc[c].x + vc[c].y) + (vc[c].z + vc[c].w);
#pragma unroll
            for (int i = 0; i < 8; i++) {
                float4 h = Bf[(8 + i) * TILE + ri];
                if (role == 1) { if (i < 4) acc[36 + i] += (h.x + h.y) + (h.z + h.w); }
                else           { if (i >= 4) acc[36 + i - 4] += (h.x + h.y) + (h.z + h.w); }
#pragma unroll
                for (int j = 0; j < 4; j++) {
                    acc[i * 4 + j] += h.x * vc[j].x; acc[i * 4 + j] += h.y * vc[j].y;
                    acc[i * 4 + j] += h.z * vc[j].z; acc[i * 4 + j] += h.w * vc[j].w;
                }
            }
        }
    }

    if (role == 0) {
        int k = 0;
#pragma unroll
        for (int i = 0; i < 8; i++)
#pragma unroll
            for (int j = 0; j <= i; j++) {
                float v = warp_sum(acc[k]);
                if (lane == 0) atomicAdd(&rpair[i * (i + 1) / 2 + j], v);
                k++;
            }
    } else if (role == 3) {
        int k = 0;
#pragma unroll
        for (int i = 0; i < 8; i++)
#pragma unroll
            for (int j = 0; j <= i; j++) {
                const int gi = i + 8, gj = j + 8;
                float v = warp_sum(acc[k]);
                if (lane == 0) atomicAdd(&rpair[gi * (gi + 1) / 2 + gj], v);
                k++;
            }
    } else {
        const int cb = (role == 1) ? 0 : 4;
#pragma unroll
        for (int i = 0; i < 8; i++)
#pragma unroll
            for (int j = 0; j < 4; j++) {
                float v = warp_sum(acc[i * 4 + j]);
                const int r = i + 8;
                if (lane == 0) atomicAdd(&rpair[r * (r + 1) / 2 + cb + j], v);
            }
#pragma unroll
        for (int c = 0; c < 4; c++) {
            float v = warp_sum(acc[32 + c]);
            if (lane == 0) atomicAdd(&rsum[cb + c], v);
        }
        const int hb = (role == 1) ? 8 : 12;
#pragma unroll
        for (int c = 0; c < 4; c++) {
            float v = warp_sum(acc[36 + c]);
            if (lane == 0) atomicAdd(&rsum[hb + c], v);
        }
    }
    __syncthreads();

    for (int i = tid; i < PAIRS; i += 256) g_pprod[g][by][i] = rpair[i];
    if (tid < GS) g_psum[g][by][tid] = rsum[tid];
}

// ---------------------------------------------------------------------------
// solve (unchanged from R5)
// ---------------------------------------------------------------------------
__global__ void solve_kernel() {
    const int tid  = threadIdx.x;     // 512
    const int g    = tid >> 5;
    const int lane = tid & 31;

    __shared__ float SP[NGRP][PAIRS];
    __shared__ float MU[NGRP][GS];
    __shared__ float A [NGRP][GS][GS + 1];
    __shared__ float Wm[NGRP][GS][GS + 1];

    const float n   = (float)NPOS;
    const float nm1 = (float)(NPOS - 1);

    for (int item = tid; item < NGRP * (PAIRS + GS); item += 512) {
        const int gg = item / (PAIRS + GS);
        const int r  = item - gg * (PAIRS + GS);
        float sum = 0.0f;
        if (r < PAIRS) {
#pragma unroll
            for (int by = 0; by < STATS_BY; by++) sum += g_pprod[gg][by][r];
            SP[gg][r] = sum;
        } else {
#pragma unroll
            for (int by = 0; by < STATS_BY; by++) sum += g_psum[gg][by][r - PAIRS];
            MU[gg][r - PAIRS] = sum / n;
        }
    }
    __syncthreads();

    for (int k = lane; k < PAIRS; k += 32) {
        int i = (int)((sqrtf(8.0f * k + 1.0f) - 1.0f) * 0.5f);
        while ((i + 1) * (i + 2) / 2 <= k) i++;
        while (i * (i + 1) / 2 > k) i--;
        const int j = k - i * (i + 1) / 2;
        float cv = (SP[g][k] - n * MU[g][i] * MU[g][j]) / nm1;
        cv *= (1.0f - EPS_W);
        if (i == j) cv += EPS_W;
        A[g][i][j] = cv;
    }
    __syncwarp();

    for (int j = 0; j < GS; j++) {
        if (lane == j) A[g][j][j] = sqrtf(A[g][j][j]);
        __syncwarp();
        const float dinv = 1.0f / A[g][j][j];
        if (lane > j && lane < GS) A[g][lane][j] *= dinv;
        __syncwarp();
        if (lane > j && lane < GS) {
            const float lij = A[g][lane][j];
            for (int k2 = j + 1; k2 <= lane; k2++)
                A[g][lane][k2] -= lij * A[g][k2][j];
        }
        __syncwarp();
    }

    if (lane < GS) {
        const int j = lane;
        Wm[g][j][j] = 1.0f / A[g][j][j];
        for (int i = j + 1; i < GS; i++) {
            float s2 = 0.0f;
            for (int k2 = j; k2 < i; k2++) s2 += A[g][i][k2] * Wm[g][k2][j];
            Wm[g][i][j] = -s2 / A[g][i][i];
        }
    }
    __syncwarp();

    if (lane < GS) {
        float bb = 0.0f;
        for (int j = 0; j <= lane; j++) bb += Wm[g][lane][j] * MU[g][j];
        g_b[g][lane] = bb;
    }
    for (int e = lane; e < GS * GS; e += 32) {
        const int i = e >> 4, j = e & 15;
        g_W[g][e] = (j <= i) ? Wm[g][i][j] : 0.0f;
    }
}

// ---------------------------------------------------------------------------
// apply: two-half structure exploiting triangular W.
//   phase 1: load ch0-7 (8x float4, MLP 8), emit rows 0-7, start partials
//            for rows 8-15 over cols 0-7.
//   phase 2: load ch8-15 into the same regs, finish rows 8-15.
// Peak live ~85 regs -> 2 blocks/SM WITHOUT spills.
// ---------------------------------------------------------------------------
__global__ void __launch_bounds__(256, 2) apply_kernel(const float4* __restrict__ x4,
                                                       float4* __restrict__ o4) {
    const int g   = blockIdx.x;
    const int tid = threadIdx.x;

    __shared__ float Ws[GS * GS];
    __shared__ float bs[GS];
    Ws[tid] = g_W[g][tid];
    if (tid < GS) bs[tid] = g_b[g][tid];
    __syncthreads();

    const int step = APPLY_BY * 256;
    for (int pos = blockIdx.y * 256 + tid; pos < NPOS4; pos += step) {
        const int m = pos / HW4;
        const int q = pos - m * HW4;
        const int base = (m * D_FEAT + g * GS) * HW4 + q;

        float4 v[8];
#pragma unroll
        for (int c = 0; c < 8; c++) v[c] = x4[base + c * HW4];

        // rows 0-7 (need only cols 0-7): emit immediately
#pragma unroll
        for (int i = 0; i < 8; i++) {
            const float bi = bs[i];
            float4 a = make_float4(-bi, -bi, -bi, -bi);
#pragma unroll
            for (int j = 0; j <= i; j++) {
                const float w = Ws[i * GS + j];
                a.x += w * v[j].x; a.y += w * v[j].y;
                a.z += w * v[j].z; a.w += w * v[j].w;
            }
            o4[base + i * HW4] = a;
        }

        // rows 8-15 partials over cols 0-7
        float4 p[8];
#pragma unroll
        for (int i = 0; i < 8; i++) {
            const float bi = bs[8 + i];
            float4 a = make_float4(-bi, -bi, -bi, -bi);
#pragma unroll
            for (int j = 0; j < 8; j++) {
                const float w = Ws[(8 + i) * GS + j];
                a.x += w * v[j].x; a.y += w * v[j].y;
                a.z += w * v[j].z; a.w += w * v[j].w;
            }
            p[i] = a;
        }

        // second half of channels
#pragma unroll
        for (int c = 0; c < 8; c++) v[c] = x4[base + (8 + c) * HW4];

#pragma unroll
        for (int i = 0; i < 8; i++) {
            float4 a = p[i];
#pragma unroll
            for (int j = 0; j <= i; j++) {
                const float w = Ws[(8 + i) * GS + 8 + j];
                a.x += w * v[j].x; a.y += w * v[j].y;
                a.z += w * v[j].z; a.w += w * v[j].w;
            }
            o4[base + (8 + i) * HW4] = a;
        }
    }
}

// ---------------------------------------------------------------------------
extern "C" void kernel_launch(void* const* d_in, const int* in_sizes, int n_in,
                              void* d_out, int out_size) {
    const float4* x = (const float4*)d_in[0];
    float4* out = (float4*)d_out;

    stats_kernel<<<dim3(NGRP, STATS_BY), 256>>>(x);
    solve_kernel<<<1, 512>>>();
    apply_kernel<<<dim3(NGRP, APPLY_BY), 256>>>(x, out);
}

// round 7
// speedup vs baseline: 1.5080x; 1.5080x over previous
#include <cuda_runtime.h>
#include <cuda_bf16.h>
#include <math.h>

#define D_FEAT    256
#define HW4       784             // float4 units per channel-image
#define NGRP      16
#define GS        16
#define NPOS      100352
#define NPOS4     25088
#define PAIRS     136
#define EPS_W     1e-6f

#define STATS_BY  27              // 16*27 = 432 blocks = 1 wave @ 3/SM
#define TILE      64              // float4 positions per smem tile
#define CHUNK     930             // ceil(NPOS4/27)
#define NTILES    15              // ceil(CHUNK/TILE)
#define APPLY_BY  18              // 16*18 = 288 blocks = 1 wave @ 2/SM

// Scratch (per-block partials, fully overwritten every launch)
__device__ float g_psum [NGRP][STATS_BY][GS];
__device__ float g_pprod[NGRP][STATS_BY][PAIRS];
__device__ float g_W[NGRP][GS * GS];
__device__ float g_b[NGRP][GS];

__device__ __forceinline__ float warp_sum(float v) {
    v += __shfl_down_sync(0xffffffffu, v, 16);
    v += __shfl_down_sync(0xffffffffu, v, 8);
    v += __shfl_down_sync(0xffffffffu, v, 4);
    v += __shfl_down_sync(0xffffffffu, v, 2);
    v += __shfl_down_sync(0xffffffffu, v, 1);
    return v;
}

__device__ __forceinline__ void stcs4(float4* p, float4 v) {
    asm volatile("st.global.cs.v4.f32 [%0], {%1,%2,%3,%4};"
                 :: "l"(p), "f"(v.x), "f"(v.y), "f"(v.z), "f"(v.w) : "memory");
}

// ---------------------------------------------------------------------------
// stats: cp.async-staged smem tiles, double buffered, 3 blocks/SM.
// (identical to R5 — best measured 31.5us)
// ---------------------------------------------------------------------------
__global__ void __launch_bounds__(256, 3) stats_kernel(const float4* __restrict__ x4) {
    const int g   = blockIdx.x;
    const int by  = blockIdx.y;
    const int tid = threadIdx.x;

    const int P0 = by * CHUNK;
    const int P1 = (P0 + CHUNK < NPOS4) ? (P0 + CHUNK) : NPOS4;

    __shared__ float4 sbuf[2][GS * TILE];          // 2 x 16 KB
    __shared__ float rsum[GS];
    __shared__ float rpair[PAIRS];
    for (int i = tid; i < GS; i += 256) rsum[i] = 0.0f;
    for (int i = tid; i < PAIRS; i += 256) rpair[i] = 0.0f;

    const int li  = tid & 63;
    const int c0  = (tid >> 6) * 4;
    const int gch = g * GS;
    const unsigned sb = (unsigned)__cvta_generic_to_shared(&sbuf[0][0]);

    {
        const int pos = P0 + li;
        const unsigned sz = (pos < P1) ? 16u : 0u;
        const int pc = (pos < P1) ? pos : P0;
        const int m = pc / HW4;
        const int q = pc - m * HW4;
        const float4* src = x4 + (size_t)(m * D_FEAT + gch + c0) * HW4 + q;
        const unsigned dst = sb + (unsigned)((c0 * TILE + li) * 16);
#pragma unroll
        for (int j = 0; j < 4; j++)
            asm volatile("cp.async.cg.shared.global [%0], [%1], 16, %2;"
                         :: "r"(dst + j * TILE * 16), "l"(src + j * HW4), "r"(sz));
        asm volatile("cp.async.commit_group;" ::: "memory");
    }

    const int role = tid >> 6;
    const int ri   = tid & 63;
    const int lane = tid & 31;

    float acc[40];
#pragma unroll
    for (int i = 0; i < 40; i++) acc[i] = 0.0f;

    for (int t = 0; t < NTILES; t++) {
        asm volatile("cp.async.wait_group 0;" ::: "memory");
        __syncthreads();

        if (t + 1 < NTILES) {
            const int pos = P0 + (t + 1) * TILE + li;
            const unsigned sz = (pos < P1) ? 16u : 0u;
            const int pc = (pos < P1) ? pos : P0;
            const int m = pc / HW4;
            const int q = pc - m * HW4;
            const float4* src = x4 + (size_t)(m * D_FEAT + gch + c0) * HW4 + q;
            const unsigned dst = sb +
                (unsigned)((((t + 1) & 1) * GS * TILE + c0 * TILE + li) * 16);
#pragma unroll
            for (int j = 0; j < 4; j++)
                asm volatile("cp.async.cg.shared.global [%0], [%1], 16, %2;"
                             :: "r"(dst + j * TILE * 16), "l"(src + j * HW4), "r"(sz));
            asm volatile("cp.async.commit_group;" ::: "memory");
        }

        const float4* Bf = sbuf[t & 1];

        if (role == 0) {
            float4 v[8];
#pragma unroll
            for (int c = 0; c < 8; c++) v[c] = Bf[c * TILE + ri];
            int k = 0;
#pragma unroll
            for (int i = 0; i < 8; i++)
#pragma unroll
                for (int j = 0; j <= i; j++) {
                    acc[k] += v[i].x * v[j].x; acc[k] += v[i].y * v[j].y;
                    acc[k] += v[i].z * v[j].z; acc[k] += v[i].w * v[j].w;
                    k++;
                }
        } else if (role == 3) {
            float4 v[8];
#pragma unroll
            for (int c = 0; c < 8; c++) v[c] = Bf[(c + 8) * TILE + ri];
            int k = 0;
#pragma unroll
            for (int i = 0; i < 8; i++)
#pragma unroll
                for (int j = 0; j <= i; j++) {
                    acc[k] += v[i].x * v[j].x; acc[k] += v[i].y * v[j].y;
                    acc[k] += v[i].z * v[j].z; acc[k] += v[i].w * v[j].w;
                    k++;
                }
        } else {
            const int cb = (role == 1) ? 0 : 4;
            float4 vc[4];
#pragma unroll
            for (int c = 0; c < 4; c++) vc[c] = Bf[(cb + c) * TILE + ri];
#pragma unroll
            for (int c = 0; c < 4; c++)
                acc[32 + c] += (vc[c].x + vc[c].y) + (vc[c].z + vc[c].w);
#pragma unroll
            for (int i = 0; i < 8; i++) {
                float4 h = Bf[(8 + i) * TILE + ri];
                if (role == 1) { if (i < 4) acc[36 + i] += (h.x + h.y) + (h.z + h.w); }
                else           { if (i >= 4) acc[36 + i - 4] += (h.x + h.y) + (h.z + h.w); }
#pragma unroll
                for (int j = 0; j < 4; j++) {
                    acc[i * 4 + j] += h.x * vc[j].x; acc[i * 4 + j] += h.y * vc[j].y;
                    acc[i * 4 + j] += h.z * vc[j].z; acc[i * 4 + j] += h.w * vc[j].w;
                }
            }
        }
    }

    if (role == 0) {
        int k = 0;
#pragma unroll
        for (int i = 0; i < 8; i++)
#pragma unroll
            for (int j = 0; j <= i; j++) {
                float v = warp_sum(acc[k]);
                if (lane == 0) atomicAdd(&rpair[i * (i + 1) / 2 + j], v);
                k++;
            }
    } else if (role == 3) {
        int k = 0;
#pragma unroll
        for (int i = 0; i < 8; i++)
#pragma unroll
            for (int j = 0; j <= i; j++) {
                const int gi = i + 8, gj = j + 8;
                float v = warp_sum(acc[k]);
                if (lane == 0) atomicAdd(&rpair[gi * (gi + 1) / 2 + gj], v);
                k++;
            }
    } else {
        const int cb = (role == 1) ? 0 : 4;
#pragma unroll
        for (int i = 0; i < 8; i++)
#pragma unroll
            for (int j = 0; j < 4; j++) {
                float v = warp_sum(acc[i * 4 + j]);
                const int r = i + 8;
                if (lane == 0) atomicAdd(&rpair[r * (r + 1) / 2 + cb + j], v);
            }
#pragma unroll
        for (int c = 0; c < 4; c++) {
            float v = warp_sum(acc[32 + c]);
            if (lane == 0) atomicAdd(&rsum[cb + c], v);
        }
        const int hb = (role == 1) ? 8 : 12;
#pragma unroll
        for (int c = 0; c < 4; c++) {
            float v = warp_sum(acc[36 + c]);
            if (lane == 0) atomicAdd(&rsum[hb + c], v);
        }
    }
    __syncthreads();

    for (int i = tid; i < PAIRS; i += 256) g_pprod[g][by][i] = rpair[i];
    if (tid < GS) g_psum[g][by][tid] = rsum[tid];
}

// ---------------------------------------------------------------------------
// solve (unchanged)
// ---------------------------------------------------------------------------
__global__ void solve_kernel() {
    const int tid  = threadIdx.x;     // 512
    const int g    = tid >> 5;
    const int lane = tid & 31;

    __shared__ float SP[NGRP][PAIRS];
    __shared__ float MU[NGRP][GS];
    __shared__ float A [NGRP][GS][GS + 1];
    __shared__ float Wm[NGRP][GS][GS + 1];

    const float n   = (float)NPOS;
    const float nm1 = (float)(NPOS - 1);

    for (int item = tid; item < NGRP * (PAIRS + GS); item += 512) {
        const int gg = item / (PAIRS + GS);
        const int r  = item - gg * (PAIRS + GS);
        float sum = 0.0f;
        if (r < PAIRS) {
#pragma unroll
            for (int by = 0; by < STATS_BY; by++) sum += g_pprod[gg][by][r];
            SP[gg][r] = sum;
        } else {
#pragma unroll
            for (int by = 0; by < STATS_BY; by++) sum += g_psum[gg][by][r - PAIRS];
            MU[gg][r - PAIRS] = sum / n;
        }
    }
    __syncthreads();

    for (int k = lane; k < PAIRS; k += 32) {
        int i = (int)((sqrtf(8.0f * k + 1.0f) - 1.0f) * 0.5f);
        while ((i + 1) * (i + 2) / 2 <= k) i++;
        while (i * (i + 1) / 2 > k) i--;
        const int j = k - i * (i + 1) / 2;
        float cv = (SP[g][k] - n * MU[g][i] * MU[g][j]) / nm1;
        cv *= (1.0f - EPS_W);
        if (i == j) cv += EPS_W;
        A[g][i][j] = cv;
    }
    __syncwarp();

    for (int j = 0; j < GS; j++) {
        if (lane == j) A[g][j][j] = sqrtf(A[g][j][j]);
        __syncwarp();
        const float dinv = 1.0f / A[g][j][j];
        if (lane > j && lane < GS) A[g][lane][j] *= dinv;
        __syncwarp();
        if (lane > j && lane < GS) {
            const float lij = A[g][lane][j];
            for (int k2 = j + 1; k2 <= lane; k2++)
                A[g][lane][k2] -= lij * A[g][k2][j];
        }
        __syncwarp();
    }

    if (lane < GS) {
        const int j = lane;
        Wm[g][j][j] = 1.0f / A[g][j][j];
        for (int i = j + 1; i < GS; i++) {
            float s2 = 0.0f;
            for (int k2 = j; k2 < i; k2++) s2 += A[g][i][k2] * Wm[g][k2][j];
            Wm[g][i][j] = -s2 / A[g][i][i];
        }
    }
    __syncwarp();

    if (lane < GS) {
        float bb = 0.0f;
        for (int j = 0; j <= lane; j++) bb += Wm[g][lane][j] * MU[g][j];
        g_b[g][lane] = bb;
    }
    for (int e = lane; e < GS * GS; e += 32) {
        const int i = e >> 4, j = e & 15;
        g_W[g][e] = (j <= i) ? Wm[g][i][j] : 0.0f;
    }
}

// ---------------------------------------------------------------------------
// apply: two-half triangular structure, no spills @128 regs, evict-first
// stores so streaming output does not evict the L2-resident input.
// ---------------------------------------------------------------------------
__global__ void __launch_bounds__(256, 2) apply_kernel(const float4* __restrict__ x4,
                                                       float4* __restrict__ o4) {
    const int g   = blockIdx.x;
    const int tid = threadIdx.x;

    __shared__ float Ws[GS * GS];
    __shared__ float bs[GS];
    Ws[tid] = g_W[g][tid];
    if (tid < GS) bs[tid] = g_b[g][tid];
    __syncthreads();

    const int step = APPLY_BY * 256;
    for (int pos = blockIdx.y * 256 + tid; pos < NPOS4; pos += step) {
        const int m = pos / HW4;
        const int q = pos - m * HW4;
        const int base = (m * D_FEAT + g * GS) * HW4 + q;

        float4 v[8];
#pragma unroll
        for (int c = 0; c < 8; c++) v[c] = x4[base + c * HW4];

        // rows 0-7 (need only cols 0-7): emit immediately
#pragma unroll
        for (int i = 0; i < 8; i++) {
            const float bi = bs[i];
            float4 a = make_float4(-bi, -bi, -bi, -bi);
#pragma unroll
            for (int j = 0; j <= i; j++) {
                const float w = Ws[i * GS + j];
                a.x += w * v[j].x; a.y += w * v[j].y;
                a.z += w * v[j].z; a.w += w * v[j].w;
            }
            stcs4(o4 + base + i * HW4, a);
        }

        // rows 8-15 partials over cols 0-7
        float4 p[8];
#pragma unroll
        for (int i = 0; i < 8; i++) {
            const float bi = bs[8 + i];
            float4 a = make_float4(-bi, -bi, -bi, -bi);
#pragma unroll
            for (int j = 0; j < 8; j++) {
                const float w = Ws[(8 + i) * GS + j];
                a.x += w * v[j].x; a.y += w * v[j].y;
                a.z += w * v[j].z; a.w += w * v[j].w;
            }
            p[i] = a;
        }

        // second half of channels
#pragma unroll
        for (int c = 0; c < 8; c++) v[c] = x4[base + (8 + c) * HW4];

#pragma unroll
        for (int i = 0; i < 8; i++) {
            float4 a = p[i];
#pragma unroll
            for (int j = 0; j <= i; j++) {
                const float w = Ws[(8 + i) * GS + 8 + j];
                a.x += w * v[j].x; a.y += w * v[j].y;
                a.z += w * v[j].z; a.w += w * v[j].w;
            }
            stcs4(o4 + base + (8 + i) * HW4, a);
        }
    }
}

// ---------------------------------------------------------------------------
extern "C" void kernel_launch(void* const* d_in, const int* in_sizes, int n_in,
                              void* d_out, int out_size) {
    const float4* x = (const float4*)d_in[0];
    float4* out = (float4*)d_out;

    stats_kernel<<<dim3(NGRP, STATS_BY), 256>>>(x);
    solve_kernel<<<1, 512>>>();
    apply_kernel<<<dim3(NGRP, APPLY_BY), 256>>>(x, out);
}

// round 11
// speedup vs baseline: 1.5847x; 1.0508x over previous
#include <cuda_runtime.h>
#include <cuda_bf16.h>
#include <math.h>

#define D_FEAT    256
#define HW4       784             // float4 units per channel-image
#define NGRP      16
#define GS        16
#define NPOS      100352
#define NPOS4     25088
#define PAIRS     136
#define EPS_W     1e-6f

#define STATS_BY  27              // 16*27 = 432 blocks = 1 wave @ 3/SM
#define TILE      64              // float4 positions per smem tile
#define CHUNK     930             // ceil(NPOS4/27)
#define NTILES    15              // ceil(CHUNK/TILE)
#define NBUF      3               // pipeline depth (wait_group 1)
#define APPLY_BY  18              // 16*18 = 288 blocks = 1 wave @ 2/SM

#define STATS_DSMEM (NBUF * GS * TILE * 16)   // 49152 bytes

// Scratch (per-block partials, fully overwritten every launch)
__device__ float g_psum [NGRP][STATS_BY][GS];
__device__ float g_pprod[NGRP][STATS_BY][PAIRS];
__device__ float g_W[NGRP][GS * GS];
__device__ float g_b[NGRP][GS];

__device__ __forceinline__ float warp_sum(float v) {
    v += __shfl_down_sync(0xffffffffu, v, 16);
    v += __shfl_down_sync(0xffffffffu, v, 8);
    v += __shfl_down_sync(0xffffffffu, v, 4);
    v += __shfl_down_sync(0xffffffffu, v, 2);
    v += __shfl_down_sync(0xffffffffu, v, 1);
    return v;
}

__device__ __forceinline__ void stcs4(float4* p, float4 v) {
    asm volatile("st.global.cs.v4.f32 [%0], {%1,%2,%3,%4};"
                 :: "l"(p), "f"(v.x), "f"(v.y), "f"(v.z), "f"(v.w) : "memory");
}

// ---------------------------------------------------------------------------
// stats: 3-stage cp.async pipeline (wait_group 1): each load gets ~2 compute
// phases to land instead of 1. Tile ring lives in dynamic smem (48KB).
// ---------------------------------------------------------------------------
__global__ void __launch_bounds__(256, 3) stats_kernel(const float4* __restrict__ x4) {
    extern __shared__ float4 dsbuf[];              // NBUF * GS * TILE
    const int g   = blockIdx.x;
    const int by  = blockIdx.y;
    const int tid = threadIdx.x;

    const int P0 = by * CHUNK;
    const int P1 = (P0 + CHUNK < NPOS4) ? (P0 + CHUNK) : NPOS4;

    __shared__ float rsum[GS];
    __shared__ float rpair[PAIRS];
    for (int i = tid; i < GS; i += 256) rsum[i] = 0.0f;
    for (int i = tid; i < PAIRS; i += 256) rpair[i] = 0.0f;

    const int li  = tid & 63;
    const int c0  = (tid >> 6) * 4;
    const int gch = g * GS;
    const unsigned sb = (unsigned)__cvta_generic_to_shared(dsbuf);

    // issue one tile's loads into ring buffer `buf`
    auto issue_tile = [&](int t, int buf) {
        const int pos = P0 + t * TILE + li;
        const unsigned sz = (pos < P1) ? 16u : 0u;
        const int pc = (pos < P1) ? pos : P0;
        const int m = pc / HW4;
        const int q = pc - m * HW4;
        const float4* src = x4 + (size_t)(m * D_FEAT + gch + c0) * HW4 + q;
        const unsigned dst = sb + (unsigned)((buf * GS * TILE + c0 * TILE + li) * 16);
#pragma unroll
        for (int j = 0; j < 4; j++)
            asm volatile("cp.async.cg.shared.global [%0], [%1], 16, %2;"
                         :: "r"(dst + j * TILE * 16), "l"(src + j * HW4), "r"(sz));
        asm volatile("cp.async.commit_group;" ::: "memory");
    };

    // prologue: two tiles in flight
    issue_tile(0, 0);
    issue_tile(1, 1);

    const int role = tid >> 6;
    const int ri   = tid & 63;
    const int lane = tid & 31;

    float acc[40];
#pragma unroll
    for (int i = 0; i < 40; i++) acc[i] = 0.0f;

    for (int t = 0; t < NTILES; t++) {
        asm volatile("cp.async.wait_group 1;" ::: "memory");   // T_t done, T_{t+1} may fly
        __syncthreads();

        if (t + 2 < NTILES) issue_tile(t + 2, (t + 2) % NBUF);

        const float4* Bf = dsbuf + (t % NBUF) * GS * TILE;

        if (role == 0) {
            float4 v[8];
#pragma unroll
            for (int c = 0; c < 8; c++) v[c] = Bf[c * TILE + ri];
            int k = 0;
#pragma unroll
            for (int i = 0; i < 8; i++)
#pragma unroll
                for (int j = 0; j <= i; j++) {
                    acc[k] += v[i].x * v[j].x; acc[k] += v[i].y * v[j].y;
                    acc[k] += v[i].z * v[j].z; acc[k] += v[i].w * v[j].w;
                    k++;
                }
        } else if (role == 3) {
            float4 v[8];
#pragma unroll
            for (int c = 0; c < 8; c++) v[c] = Bf[(c + 8) * TILE + ri];
            int k = 0;
#pragma unroll
            for (int i = 0; i < 8; i++)
#pragma unroll
                for (int j = 0; j <= i; j++) {
                    acc[k] += v[i].x * v[j].x; acc[k] += v[i].y * v[j].y;
                    acc[k] += v[i].z * v[j].z; acc[k] += v[i].w * v[j].w;
                    k++;
                }
        } else {
            const int cb = (role == 1) ? 0 : 4;
            float4 vc[4];
#pragma unroll
            for (int c = 0; c < 4; c++) vc[c] = Bf[(cb + c) * TILE + ri];
#pragma unroll
            for (int c = 0; c < 4; c++)
                acc[32 + c] += (vc[c].x + vc[c].y) + (vc[c].z + vc[c].w);
#pragma unroll
            for (int i = 0; i < 8; i++) {
                float4 h = Bf[(8 + i) * TILE + ri];
                if (role == 1) { if (i < 4) acc[36 + i] += (h.x + h.y) + (h.z + h.w); }
                else           { if (i >= 4) acc[36 + i - 4] += (h.x + h.y) + (h.z + h.w); }
#pragma unroll
                for (int j = 0; j < 4; j++) {
                    acc[i * 4 + j] += h.x * vc[j].x; acc[i * 4 + j] += h.y * vc[j].y;
                    acc[i * 4 + j] += h.z * vc[j].z; acc[i * 4 + j] += h.w * vc[j].w;
                }
            }
        }
    }

    if (role == 0) {
        int k = 0;
#pragma unroll
        for (int i = 0; i < 8; i++)
#pragma unroll
            for (int j = 0; j <= i; j++) {
                float v = warp_sum(acc[k]);
                if (lane == 0) atomicAdd(&rpair[i * (i + 1) / 2 + j], v);
                k++;
            }
    } else if (role == 3) {
        int k = 0;
#pragma unroll
        for (int i = 0; i < 8; i++)
#pragma unroll
            for (int j = 0; j <= i; j++) {
                const int gi = i + 8, gj = j + 8;
                float v = warp_sum(acc[k]);
                if (lane == 0) atomicAdd(&rpair[gi * (gi + 1) / 2 + gj], v);
                k++;
            }
    } else {
        const int cb = (role == 1) ? 0 : 4;
#pragma unroll
        for (int i = 0; i < 8; i++)
#pragma unroll
            for (int j = 0; j < 4; j++) {
                float v = warp_sum(acc[i * 4 + j]);
                const int r = i + 8;
                if (lane == 0) atomicAdd(&rpair[r * (r + 1) / 2 + cb + j], v);
            }
#pragma unroll
        for (int c = 0; c < 4; c++) {
            float v = warp_sum(acc[32 + c]);
            if (lane == 0) atomicAdd(&rsum[cb + c], v);
        }
        const int hb = (role == 1) ? 8 : 12;
#pragma unroll
        for (int c = 0; c < 4; c++) {
            float v = warp_sum(acc[36 + c]);
            if (lane == 0) atomicAdd(&rsum[hb + c], v);
        }
    }
    __syncthreads();

    for (int i = tid; i < PAIRS; i += 256) g_pprod[g][by][i] = rpair[i];
    if (tid < GS) g_psum[g][by][tid] = rsum[tid];
}

// ---------------------------------------------------------------------------
// solve (unchanged)
// ---------------------------------------------------------------------------
__global__ void solve_kernel() {
    const int tid  = threadIdx.x;     // 512
    const int g    = tid >> 5;
    const int lane = tid & 31;

    __shared__ float SP[NGRP][PAIRS];
    __shared__ float MU[NGRP][GS];
    __shared__ float A [NGRP][GS][GS + 1];
    __shared__ float Wm[NGRP][GS][GS + 1];

    const float n   = (float)NPOS;
    const float nm1 = (float)(NPOS - 1);

    for (int item = tid; item < NGRP * (PAIRS + GS); item += 512) {
        const int gg = item / (PAIRS + GS);
        const int r  = item - gg * (PAIRS + GS);
        float sum = 0.0f;
        if (r < PAIRS) {
#pragma unroll
            for (int by = 0; by < STATS_BY; by++) sum += g_pprod[gg][by][r];
            SP[gg][r] = sum;
        } else {
#pragma unroll
            for (int by = 0; by < STATS_BY; by++) sum += g_psum[gg][by][r - PAIRS];
            MU[gg][r - PAIRS] = sum / n;
        }
    }
    __syncthreads();

    for (int k = lane; k < PAIRS; k += 32) {
        int i = (int)((sqrtf(8.0f * k + 1.0f) - 1.0f) * 0.5f);
        while ((i + 1) * (i + 2) / 2 <= k) i++;
        while (i * (i + 1) / 2 > k) i--;
        const int j = k - i * (i + 1) / 2;
        float cv = (SP[g][k] - n * MU[g][i] * MU[g][j]) / nm1;
        cv *= (1.0f - EPS_W);
        if (i == j) cv += EPS_W;
        A[g][i][j] = cv;
    }
    __syncwarp();

    for (int j = 0; j < GS; j++) {
        if (lane == j) A[g][j][j] = sqrtf(A[g][j][j]);
        __syncwarp();
        const float dinv = 1.0f / A[g][j][j];
        if (lane > j && lane < GS) A[g][lane][j] *= dinv;
        __syncwarp();
        if (lane > j && lane < GS) {
            const float lij = A[g][lane][j];
            for (int k2 = j + 1; k2 <= lane; k2++)
                A[g][lane][k2] -= lij * A[g][k2][j];
        }
        __syncwarp();
    }

    if (lane < GS) {
        const int j = lane;
        Wm[g][j][j] = 1.0f / A[g][j][j];
        for (int i = j + 1; i < GS; i++) {
            float s2 = 0.0f;
            for (int k2 = j; k2 < i; k2++) s2 += A[g][i][k2] * Wm[g][k2][j];
            Wm[g][i][j] = -s2 / A[g][i][i];
        }
    }
    __syncwarp();

    if (lane < GS) {
        float bb = 0.0f;
        for (int j = 0; j <= lane; j++) bb += Wm[g][lane][j] * MU[g][j];
        g_b[g][lane] = bb;
    }
    for (int e = lane; e < GS * GS; e += 32) {
        const int i = e >> 4, j = e & 15;
        g_W[g][e] = (j <= i) ? Wm[g][i][j] : 0.0f;
    }
}

// ---------------------------------------------------------------------------
// apply: two-half triangular structure, no spills @128 regs, evict-first
// stores (unchanged from R7 WIN).
// ---------------------------------------------------------------------------
__global__ void __launch_bounds__(256, 2) apply_kernel(const float4* __restrict__ x4,
                                                       float4* __restrict__ o4) {
    const int g   = blockIdx.x;
    const int tid = threadIdx.x;

    __shared__ float Ws[GS * GS];
    __shared__ float bs[GS];
    Ws[tid] = g_W[g][tid];
    if (tid < GS) bs[tid] = g_b[g][tid];
    __syncthreads();

    const int step = APPLY_BY * 256;
    for (int pos = blockIdx.y * 256 + tid; pos < NPOS4; pos += step) {
        const int m = pos / HW4;
        const int q = pos - m * HW4;
        const int base = (m * D_FEAT + g * GS) * HW4 + q;

        float4 v[8];
#pragma unroll
        for (int c = 0; c < 8; c++) v[c] = x4[base + c * HW4];

#pragma unroll
        for (int i = 0; i < 8; i++) {
            const float bi = bs[i];
            float4 a = make_float4(-bi, -bi, -bi, -bi);
#pragma unroll
            for (int j = 0; j <= i; j++) {
                const float w = Ws[i * GS + j];
                a.x += w * v[j].x; a.y += w * v[j].y;
                a.z += w * v[j].z; a.w += w * v[j].w;
            }
            stcs4(o4 + base + i * HW4, a);
        }

        float4 p[8];
#pragma unroll
        for (int i = 0; i < 8; i++) {
            const float bi = bs[8 + i];
            float4 a = make_float4(-bi, -bi, -bi, -bi);
#pragma unroll
            for (int j = 0; j < 8; j++) {
                const float w = Ws[(8 + i) * GS + j];
                a.x += w * v[j].x; a.y += w * v[j].y;
                a.z += w * v[j].z; a.w += w * v[j].w;
            }
            p[i] = a;
        }

#pragma unroll
        for (int c = 0; c < 8; c++) v[c] = x4[base + (8 + c) * HW4];

#pragma unroll
        for (int i = 0; i < 8; i++) {
            float4 a = p[i];
#pragma unroll
            for (int j = 0; j <= i; j++) {
                const float w = Ws[(8 + i) * GS + 8 + j];
                a.x += w * v[j].x; a.y += w * v[j].y;
                a.z += w * v[j].z; a.w += w * v[j].w;
            }
            stcs4(o4 + base + (8 + i) * HW4, a);
        }
    }
}

// ---------------------------------------------------------------------------
extern "C" void kernel_launch(void* const* d_in, const int* in_sizes, int n_in,
                              void* d_out, int out_size) {
    const float4* x = (const float4*)d_in[0];
    float4* out = (float4*)d_out;

    static int smem_set = 0;
    if (!smem_set) {
        cudaFuncSetAttribute(stats_kernel,
                             cudaFuncAttributeMaxDynamicSharedMemorySize, STATS_DSMEM);
        smem_set = 1;
    }

    stats_kernel<<<dim3(NGRP, STATS_BY), 256, STATS_DSMEM>>>(x);
    solve_kernel<<<1, 512>>>();
    apply_kernel<<<dim3(NGRP, APPLY_BY), 256>>>(x, out);
}

// round 15
// speedup vs baseline: 1.6212x; 1.0231x over previous
#include <cuda_runtime.h>
#include <cuda_bf16.h>
#include <math.h>

#define D_FEAT    256
#define HW4       784             // float4 units per channel-image
#define NGRP      16
#define GS        16
#define NPOS      100352
#define NPOS4     25088
#define PAIRS     136
#define EPS_W     1e-6f

#define STATS_BY  27              // 16*27 = 432 blocks = 1 wave @ 3/SM
#define TILE      64              // float4 positions per smem tile
#define CHUNK     930             // ceil(NPOS4/27)
#define NTILES    15              // ceil(CHUNK/TILE)
#define NBUF      3               // pipeline depth (wait_group 1)
#define APPLY_BY  18              // 16*18 = 288 blocks = 1 wave @ 2/SM

#define STATS_DSMEM (NBUF * GS * TILE * 16)   // 49152 bytes

// Scratch (per-block partials, fully overwritten every launch)
__device__ float g_psum [NGRP][STATS_BY][GS];
__device__ float g_pprod[NGRP][STATS_BY][PAIRS];
__device__ float g_W[NGRP][GS * GS];
__device__ float g_b[NGRP][GS];
__device__ int   g_count[NGRP];          // zero-initialized; reset after use

__device__ __forceinline__ float warp_sum(float v) {
    v += __shfl_down_sync(0xffffffffu, v, 16);
    v += __shfl_down_sync(0xffffffffu, v, 8);
    v += __shfl_down_sync(0xffffffffu, v, 4);
    v += __shfl_down_sync(0xffffffffu, v, 2);
    v += __shfl_down_sync(0xffffffffu, v, 1);
    return v;
}

__device__ __forceinline__ void stcs4(float4* p, float4 v) {
    asm volatile("st.global.cs.v4.f32 [%0], {%1,%2,%3,%4};"
                 :: "l"(p), "f"(v.x), "f"(v.y), "f"(v.z), "f"(v.w) : "memory");
}

// ---------------------------------------------------------------------------
// stats + last-block-per-group solve.
// stats part identical to R11 (3-stage cp.async pipeline, 27.8us).
// The 27th block of each group inline-runs the solve (identical math/order).
// ---------------------------------------------------------------------------
__global__ void __launch_bounds__(256, 3) stats_kernel(const float4* __restrict__ x4) {
    extern __shared__ float4 dsbuf[];              // NBUF * GS * TILE
    const int g   = blockIdx.x;
    const int by  = blockIdx.y;
    const int tid = threadIdx.x;

    const int P0 = by * CHUNK;
    const int P1 = (P0 + CHUNK < NPOS4) ? (P0 + CHUNK) : NPOS4;

    __shared__ float rsum[GS];
    __shared__ float rpair[PAIRS];
    for (int i = tid; i < GS; i += 256) rsum[i] = 0.0f;
    for (int i = tid; i < PAIRS; i += 256) rpair[i] = 0.0f;

    const int li  = tid & 63;
    const int c0  = (tid >> 6) * 4;
    const int gch = g * GS;
    const unsigned sb = (unsigned)__cvta_generic_to_shared(dsbuf);

    auto issue_tile = [&](int t, int buf) {
        const int pos = P0 + t * TILE + li;
        const unsigned sz = (pos < P1) ? 16u : 0u;
        const int pc = (pos < P1) ? pos : P0;
        const int m = pc / HW4;
        const int q = pc - m * HW4;
        const float4* src = x4 + (size_t)(m * D_FEAT + gch + c0) * HW4 + q;
        const unsigned dst = sb + (unsigned)((buf * GS * TILE + c0 * TILE + li) * 16);
#pragma unroll
        for (int j = 0; j < 4; j++)
            asm volatile("cp.async.cg.shared.global [%0], [%1], 16, %2;"
                         :: "r"(dst + j * TILE * 16), "l"(src + j * HW4), "r"(sz));
        asm volatile("cp.async.commit_group;" ::: "memory");
    };

    issue_tile(0, 0);
    issue_tile(1, 1);

    const int role = tid >> 6;
    const int ri   = tid & 63;
    const int lane = tid & 31;

    float acc[40];
#pragma unroll
    for (int i = 0; i < 40; i++) acc[i] = 0.0f;

    for (int t = 0; t < NTILES; t++) {
        asm volatile("cp.async.wait_group 1;" ::: "memory");
        __syncthreads();

        if (t + 2 < NTILES) issue_tile(t + 2, (t + 2) % NBUF);

        const float4* Bf = dsbuf + (t % NBUF) * GS * TILE;

        if (role == 0) {
            float4 v[8];
#pragma unroll
            for (int c = 0; c < 8; c++) v[c] = Bf[c * TILE + ri];
            int k = 0;
#pragma unroll
            for (int i = 0; i < 8; i++)
#pragma unroll
                for (int j = 0; j <= i; j++) {
                    acc[k] += v[i].x * v[j].x; acc[k] += v[i].y * v[j].y;
                    acc[k] += v[i].z * v[j].z; acc[k] += v[i].w * v[j].w;
                    k++;
                }
        } else if (role == 3) {
            float4 v[8];
#pragma unroll
            for (int c = 0; c < 8; c++) v[c] = Bf[(c + 8) * TILE + ri];
            int k = 0;
#pragma unroll
            for (int i = 0; i < 8; i++)
#pragma unroll
                for (int j = 0; j <= i; j++) {
                    acc[k] += v[i].x * v[j].x; acc[k] += v[i].y * v[j].y;
                    acc[k] += v[i].z * v[j].z; acc[k] += v[i].w * v[j].w;
                    k++;
                }
        } else {
            const int cb = (role == 1) ? 0 : 4;
            float4 vc[4];
#pragma unroll
            for (int c = 0; c < 4; c++) vc[c] = Bf[(cb + c) * TILE + ri];
#pragma unroll
            for (int c = 0; c < 4; c++)
                acc[32 + c] += (vc[c].x + vc[c].y) + (vc[c].z + vc[c].w);
#pragma unroll
            for (int i = 0; i < 8; i++) {
                float4 h = Bf[(8 + i) * TILE + ri];
                if (role == 1) { if (i < 4) acc[36 + i] += (h.x + h.y) + (h.z + h.w); }
                else           { if (i >= 4) acc[36 + i - 4] += (h.x + h.y) + (h.z + h.w); }
#pragma unroll
                for (int j = 0; j < 4; j++) {
                    acc[i * 4 + j] += h.x * vc[j].x; acc[i * 4 + j] += h.y * vc[j].y;
                    acc[i * 4 + j] += h.z * vc[j].z; acc[i * 4 + j] += h.w * vc[j].w;
                }
            }
        }
    }

    if (role == 0) {
        int k = 0;
#pragma unroll
        for (int i = 0; i < 8; i++)
#pragma unroll
            for (int j = 0; j <= i; j++) {
                float v = warp_sum(acc[k]);
                if (lane == 0) atomicAdd(&rpair[i * (i + 1) / 2 + j], v);
                k++;
            }
    } else if (role == 3) {
        int k = 0;
#pragma unroll
        for (int i = 0; i < 8; i++)
#pragma unroll
            for (int j = 0; j <= i; j++) {
                const int gi = i + 8, gj = j + 8;
                float v = warp_sum(acc[k]);
                if (lane == 0) atomicAdd(&rpair[gi * (gi + 1) / 2 + gj], v);
                k++;
            }
    } else {
        const int cb = (role == 1) ? 0 : 4;
#pragma unroll
        for (int i = 0; i < 8; i++)
#pragma unroll
            for (int j = 0; j < 4; j++) {
                float v = warp_sum(acc[i * 4 + j]);
                const int r = i + 8;
                if (lane == 0) atomicAdd(&rpair[r * (r + 1) / 2 + cb + j], v);
            }
#pragma unroll
        for (int c = 0; c < 4; c++) {
            float v = warp_sum(acc[32 + c]);
            if (lane == 0) atomicAdd(&rsum[cb + c], v);
        }
        const int hb = (role == 1) ? 8 : 12;
#pragma unroll
        for (int c = 0; c < 4; c++) {
            float v = warp_sum(acc[36 + c]);
            if (lane == 0) atomicAdd(&rsum[hb + c], v);
        }
    }
    __syncthreads();

    for (int i = tid; i < PAIRS; i += 256) g_pprod[g][by][i] = rpair[i];
    if (tid < GS) g_psum[g][by][tid] = rsum[tid];

    // ---- last-block-per-group inline solve --------------------------------
    __shared__ int is_last;
    __threadfence();
    if (tid == 0) {
        int old = atomicAdd(&g_count[g], 1);
        is_last = (old == STATS_BY - 1);
    }
    __syncthreads();
    if (!is_last) return;
    if (tid == 0) g_count[g] = 0;                  // reset for next replay

    __shared__ float SP[PAIRS];
    __shared__ float MUs[GS];
    __shared__ float A [GS][GS + 1];
    __shared__ float Wm[GS][GS + 1];

    const float n   = (float)NPOS;
    const float nm1 = (float)(NPOS - 1);

    for (int r = tid; r < PAIRS + GS; r += 256) {
        float sum = 0.0f;
        if (r < PAIRS) {
#pragma unroll
            for (int b2 = 0; b2 < STATS_BY; b2++) sum += g_pprod[g][b2][r];
            SP[r] = sum;
        } else {
#pragma unroll
            for (int b2 = 0; b2 < STATS_BY; b2++) sum += g_psum[g][b2][r - PAIRS];
            MUs[r - PAIRS] = sum / n;
        }
    }
    __syncthreads();

    if (tid < 32) {
        const int ln = tid;
        for (int k = ln; k < PAIRS; k += 32) {
            int i = (int)((sqrtf(8.0f * k + 1.0f) - 1.0f) * 0.5f);
            while ((i + 1) * (i + 2) / 2 <= k) i++;
            while (i * (i + 1) / 2 > k) i--;
            const int j = k - i * (i + 1) / 2;
            float cv = (SP[k] - n * MUs[i] * MUs[j]) / nm1;
            cv *= (1.0f - EPS_W);
            if (i == j) cv += EPS_W;
            A[i][j] = cv;
        }
        __syncwarp();

        for (int j = 0; j < GS; j++) {
            if (ln == j) A[j][j] = sqrtf(A[j][j]);
            __syncwarp();
            const float dinv = 1.0f / A[j][j];
            if (ln > j && ln < GS) A[ln][j] *= dinv;
            __syncwarp();
            if (ln > j && ln < GS) {
                const float lij = A[ln][j];
                for (int k2 = j + 1; k2 <= ln; k2++)
                    A[ln][k2] -= lij * A[k2][j];
            }
            __syncwarp();
        }

        if (ln < GS) {
            const int j = ln;
            Wm[j][j] = 1.0f / A[j][j];
            for (int i = j + 1; i < GS; i++) {
                float s2 = 0.0f;
                for (int k2 = j; k2 < i; k2++) s2 += A[i][k2] * Wm[k2][j];
                Wm[i][j] = -s2 / A[i][i];
            }
        }
        __syncwarp();

        if (ln < GS) {
            float bb = 0.0f;
            for (int j = 0; j <= ln; j++) bb += Wm[ln][j] * MUs[j];
            g_b[g][ln] = bb;
        }
        for (int e = ln; e < GS * GS; e += 32) {
            const int i = e >> 4, j = e & 15;
            g_W[g][e] = (j <= i) ? Wm[i][j] : 0.0f;
        }
    }
}

// ---------------------------------------------------------------------------
// apply: 16 batched float4 loads (MLP 16) + streamed single-accumulator rows.
// Peak ~85 regs -> no spills at 128-reg / 2-per-SM budget. Evict-first stores.
// ---------------------------------------------------------------------------
__global__ void __launch_bounds__(256, 2) apply_kernel(const float4* __restrict__ x4,
                                                       float4* __restrict__ o4) {
    const int g   = blockIdx.x;
    const int tid = threadIdx.x;

    __shared__ float Ws[GS * GS];
    __shared__ float bs[GS];
    Ws[tid] = g_W[g][tid];
    if (tid < GS) bs[tid] = g_b[g][tid];
    __syncthreads();

    const int step = APPLY_BY * 256;
    for (int pos = blockIdx.y * 256 + tid; pos < NPOS4; pos += step) {
        const int m = pos / HW4;
        const int q = pos - m * HW4;
        const int base = (m * D_FEAT + g * GS) * HW4 + q;

        float4 v[GS];
#pragma unroll
        for (int c = 0; c < GS; c++) v[c] = x4[base + c * HW4];

#pragma unroll
        for (int i = 0; i < GS; i++) {
            const float bi = bs[i];
            float4 a = make_float4(-bi, -bi, -bi, -bi);
#pragma unroll
            for (int j = 0; j <= i; j++) {
                const float w = Ws[i * GS + j];
                a.x += w * v[j].x; a.y += w * v[j].y;
                a.z += w * v[j].z; a.w += w * v[j].w;
            }
            stcs4(o4 + base + i * HW4, a);
        }
    }
}

// ---------------------------------------------------------------------------
extern "C" void kernel_launch(void* const* d_in, const int* in_sizes, int n_in,
                              void* d_out, int out_size) {
    const float4* x = (const float4*)d_in[0];
    float4* out = (float4*)d_out;

    cudaFuncSetAttribute(stats_kernel,
                         cudaFuncAttributeMaxDynamicSharedMemorySize, STATS_DSMEM);

    stats_kernel<<<dim3(NGRP, STATS_BY), 256, STATS_DSMEM>>>(x);
    apply_kernel<<<dim3(NGRP, APPLY_BY), 256>>>(x, out);
}